// round 1
// baseline (speedup 1.0000x reference)
#include <cuda_runtime.h>
#include <cuda_bf16.h>

// Problem constants
#define BB    8
#define CC    128
#define HH    64
#define WW    64
#define HWV   4096       // H*W
#define PJV   1024       // pooled positions (32*32)
#define C8    16
#define C2    64

// Scratch (device globals; no allocation allowed)
__device__ __align__(16) float          Qg[BB * HWV * C8];   // [b][i][c]   2 MB
__device__ __align__(16) float          Kg[BB * PJV * C8];   // [b][j][c]   0.5 MB
__device__ __align__(16) __nv_bfloat16  Vg[BB * PJV * C2];   // [b][j][c]   1 MB
__device__ __align__(16) float          Og[BB * HWV * C2];   // [b][i][c]   8 MB (normalized attention out)

// ---------------------------------------------------------------------------
// Kernel A: fused 1x1 convs (theta/phi/g) + 2x2 maxpool for phi/g.
// grid: 256 blocks = (b, ph rowpair), 256 threads (16x16 tile).
// smem: xs[128 ch][128 pos] fp32 (64KB) + wT[128 c][97 pad, 96 oc] (48.5KB)
// ---------------------------------------------------------------------------
__global__ __launch_bounds__(256) void convpool_kernel(
    const float* __restrict__ x,
    const float* __restrict__ wth,
    const float* __restrict__ wph,
    const float* __restrict__ wg)
{
    extern __shared__ float sm[];
    float* xs = sm;              // 128*128
    float* wT = sm + 128 * 128;  // 128*97

    const int b  = blockIdx.x >> 5;
    const int ph = blockIdx.x & 31;
    const int tid = threadIdx.x;

    // Load x tile: positions p = hl*64+w for rows h=2ph,2ph+1 (coalesced)
    const float* xbase = x + (size_t)b * (CC * HWV) + ph * 128;
    #pragma unroll
    for (int idx = tid; idx < 128 * 128; idx += 256) {
        int c = idx >> 7, p = idx & 127;
        xs[idx] = xbase[(size_t)c * HWV + p];
    }
    // Load weights transposed: oc 0..15 theta, 16..31 phi, 32..95 g
    for (int idx = tid; idx < 96 * 128; idx += 256) {
        int oc = idx >> 7, c = idx & 127;
        float v;
        if (oc < 16)      v = wth[oc * 128 + c];
        else if (oc < 32) v = wph[(oc - 16) * 128 + c];
        else              v = wg[(oc - 32) * 128 + c];
        wT[c * 97 + oc] = v;
    }
    __syncthreads();

    const int ty = tid >> 4, tx = tid & 15;
    float acc[6][8];
    #pragma unroll
    for (int n = 0; n < 6; n++)
        #pragma unroll
        for (int m = 0; m < 8; m++) acc[n][m] = 0.0f;

    #pragma unroll 4
    for (int c = 0; c < 128; c++) {
        float xv[8], wv[6];
        #pragma unroll
        for (int m = 0; m < 8; m++) xv[m] = xs[c * 128 + tx + 16 * m];
        #pragma unroll
        for (int n = 0; n < 6; n++) wv[n] = wT[c * 97 + ty + 16 * n];
        #pragma unroll
        for (int n = 0; n < 6; n++)
            #pragma unroll
            for (int m = 0; m < 8; m++)
                acc[n][m] = fmaf(wv[n], xv[m], acc[n][m]);
    }

    // theta (n==0, ch=ty) -> Q[b][i][ch], i = ph*128 + p
    #pragma unroll
    for (int m = 0; m < 8; m++) {
        int p = tx + 16 * m;
        Qg[((size_t)(b * HWV) + ph * 128 + p) * C8 + ty] = acc[0][m];
    }

    // Stage phi/g into smem (reuse xs) for 2x2 pooling
    __syncthreads();
    float* pbuf = xs;  // [80 rows][128 pos]
    #pragma unroll
    for (int n = 1; n < 6; n++) {
        int row = (n - 1) * 16 + ty;  // phi rows 0..15, g rows 16..79
        #pragma unroll
        for (int m = 0; m < 8; m++)
            pbuf[row * 128 + tx + 16 * m] = acc[n][m];
    }
    __syncthreads();

    // Pool: 80 channels x 32 pooled-cols
    for (int idx = tid; idx < 80 * 32; idx += 256) {
        int cc = idx >> 5, pw = idx & 31;
        int p0 = 2 * pw;
        float v0 = pbuf[cc * 128 + p0];
        float v1 = pbuf[cc * 128 + p0 + 1];
        float v2 = pbuf[cc * 128 + 64 + p0];
        float v3 = pbuf[cc * 128 + 64 + p0 + 1];
        float v = fmaxf(fmaxf(v0, v1), fmaxf(v2, v3));
        int pj = ph * 32 + pw;
        if (cc < 16)
            Kg[((size_t)(b * PJV) + pj) * C8 + cc] = v;
        else
            Vg[((size_t)(b * PJV) + pj) * C2 + (cc - 16)] = __float2bfloat16(v);
    }
}

// ---------------------------------------------------------------------------
// Kernel B: attention. K fp32 + V bf16 resident in smem (192KB).
// grid: (16 chunks, 8 batches) = 128 blocks, 128 threads, 2 queries/lane.
// Max-free softmax (scores bounded ~|30|), f32x2 packed FMA for V-accum.
// ---------------------------------------------------------------------------
__global__ __launch_bounds__(128, 1) void attn_kernel()
{
    extern __shared__ float sm[];
    float*        ksm = sm;                          // 1024*16 fp32  (64KB)
    unsigned int* vsm = (unsigned int*)(sm + PJV * C8);  // 1024*32 u32 (128KB)

    const int chunk = blockIdx.x;
    const int b     = blockIdx.y;
    const int tid   = threadIdx.x;

    // Load K (float4) and V (uint4) cooperatively, coalesced
    {
        const float4* src = (const float4*)(Kg + (size_t)b * PJV * C8);
        float4* dst = (float4*)ksm;
        #pragma unroll
        for (int i = tid; i < PJV * C8 / 4; i += 128) dst[i] = src[i];
        const uint4* vsrc = (const uint4*)Vg + (size_t)b * (PJV * C2 / 8);
        uint4* vdst = (uint4*)vsm;
        #pragma unroll
        for (int i = tid; i < PJV * C2 / 8; i += 128) vdst[i] = vsrc[i];
    }
    __syncthreads();

    const int q0 = chunk * 256 + 2 * tid;
    const int q1 = q0 + 1;

    // Load the two query vectors
    float qa[16], qb[16];
    {
        const float4* p0 = (const float4*)(Qg + ((size_t)(b * HWV) + q0) * C8);
        const float4* p1 = (const float4*)(Qg + ((size_t)(b * HWV) + q1) * C8);
        #pragma unroll
        for (int t = 0; t < 4; t++) {
            float4 v0 = p0[t], v1 = p1[t];
            qa[4 * t + 0] = v0.x; qa[4 * t + 1] = v0.y; qa[4 * t + 2] = v0.z; qa[4 * t + 3] = v0.w;
            qb[4 * t + 0] = v1.x; qb[4 * t + 1] = v1.y; qb[4 * t + 2] = v1.z; qb[4 * t + 3] = v1.w;
        }
    }

    unsigned long long a0[32], a1[32];
    #pragma unroll
    for (int k = 0; k < 32; k++) { a0[k] = 0ull; a1[k] = 0ull; }
    float l0 = 0.0f, l1 = 0.0f;

    #pragma unroll 2
    for (int j = 0; j < PJV; j++) {
        const float4* kj = (const float4*)(ksm + (j << 4));
        // scores (two independent fma chains per query for ILP)
        float s0a = 0.f, s0b = 0.f, s1a = 0.f, s1b = 0.f;
        #pragma unroll
        for (int t = 0; t < 4; t++) {
            float4 kk = kj[t];
            if (t & 1) {
                s0b = fmaf(kk.x, qa[4*t+0], s0b); s0b = fmaf(kk.y, qa[4*t+1], s0b);
                s0b = fmaf(kk.z, qa[4*t+2], s0b); s0b = fmaf(kk.w, qa[4*t+3], s0b);
                s1b = fmaf(kk.x, qb[4*t+0], s1b); s1b = fmaf(kk.y, qb[4*t+1], s1b);
                s1b = fmaf(kk.z, qb[4*t+2], s1b); s1b = fmaf(kk.w, qb[4*t+3], s1b);
            } else {
                s0a = fmaf(kk.x, qa[4*t+0], s0a); s0a = fmaf(kk.y, qa[4*t+1], s0a);
                s0a = fmaf(kk.z, qa[4*t+2], s0a); s0a = fmaf(kk.w, qa[4*t+3], s0a);
                s1a = fmaf(kk.x, qb[4*t+0], s1a); s1a = fmaf(kk.y, qb[4*t+1], s1a);
                s1a = fmaf(kk.z, qb[4*t+2], s1a); s1a = fmaf(kk.w, qb[4*t+3], s1a);
            }
        }
        float p0 = __expf(s0a + s0b);
        float p1 = __expf(s1a + s1b);
        l0 += p0; l1 += p1;
        unsigned long long pp0, pp1;
        {
            unsigned int p0b = __float_as_uint(p0), p1b = __float_as_uint(p1);
            asm("mov.b64 %0, {%1, %1};" : "=l"(pp0) : "r"(p0b));
            asm("mov.b64 %0, {%1, %1};" : "=l"(pp1) : "r"(p1b));
        }
        const uint4* vj = (const uint4*)(vsm + (j << 5));
        #pragma unroll
        for (int t = 0; t < 8; t++) {
            uint4 vv = vj[t];
            unsigned int u[4] = {vv.x, vv.y, vv.z, vv.w};
            #pragma unroll
            for (int e = 0; e < 4; e++) {
                unsigned int lo = u[e] << 16;
                unsigned int hi = u[e] & 0xFFFF0000u;
                unsigned long long vp;
                asm("mov.b64 %0, {%1, %2};" : "=l"(vp) : "r"(lo), "r"(hi));
                int idx = 4 * t + e;
                asm("fma.rn.f32x2 %0, %1, %2, %0;" : "+l"(a0[idx]) : "l"(vp), "l"(pp0));
                asm("fma.rn.f32x2 %0, %1, %2, %0;" : "+l"(a1[idx]) : "l"(vp), "l"(pp1));
            }
        }
    }

    // Normalize and write o (coalesced per-lane contiguous 256B rows)
    float inv0 = 1.0f / l0, inv1 = 1.0f / l1;
    float2* o0 = (float2*)(Og + ((size_t)(b * HWV) + q0) * C2);
    float2* o1 = (float2*)(Og + ((size_t)(b * HWV) + q1) * C2);
    #pragma unroll
    for (int k = 0; k < 32; k++) {
        unsigned int lo, hi;
        asm("mov.b64 {%0, %1}, %2;" : "=r"(lo), "=r"(hi) : "l"(a0[k]));
        float2 w; w.x = __uint_as_float(lo) * inv0; w.y = __uint_as_float(hi) * inv0;
        o0[k] = w;
        asm("mov.b64 {%0, %1}, %2;" : "=r"(lo), "=r"(hi) : "l"(a1[k]));
        w.x = __uint_as_float(lo) * inv1; w.y = __uint_as_float(hi) * inv1;
        o1[k] = w;
    }
}

// ---------------------------------------------------------------------------
// Kernel C: out = x + gamma * (w_o @ o).   grid (32 itiles, 8 b), 256 thr.
// ---------------------------------------------------------------------------
__global__ __launch_bounds__(256) void epilogue_kernel(
    const float* __restrict__ x,
    const float* __restrict__ wo,
    const float* __restrict__ gptr,
    float* __restrict__ out)
{
    extern __shared__ float sm[];
    float* osm = sm;                 // [128][65]
    float* wT  = sm + 128 * 65;      // [64][129] (transposed w_o)

    const int it = blockIdx.x, b = blockIdx.y;
    const int i0 = it * 128;
    const int tid = threadIdx.x;

    for (int idx = tid; idx < 128 * 64; idx += 256) {
        int p = idx >> 6, c = idx & 63;
        osm[p * 65 + c] = Og[((size_t)(b * HWV) + i0 + p) * C2 + c];
    }
    for (int idx = tid; idx < 128 * 64; idx += 256) {
        int co = idx >> 6, c = idx & 63;
        wT[c * 129 + co] = wo[idx];
    }
    __syncthreads();

    const int ty = tid >> 4, tx = tid & 15;
    float acc[8][8];
    #pragma unroll
    for (int n = 0; n < 8; n++)
        #pragma unroll
        for (int m = 0; m < 8; m++) acc[n][m] = 0.0f;

    #pragma unroll 4
    for (int c = 0; c < 64; c++) {
        float wv[8], ov[8];
        #pragma unroll
        for (int n = 0; n < 8; n++) wv[n] = wT[c * 129 + ty + 16 * n];
        #pragma unroll
        for (int m = 0; m < 8; m++) ov[m] = osm[(tx + 16 * m) * 65 + c];
        #pragma unroll
        for (int n = 0; n < 8; n++)
            #pragma unroll
            for (int m = 0; m < 8; m++)
                acc[n][m] = fmaf(wv[n], ov[m], acc[n][m]);
    }

    const float gamma = __ldg(gptr);
    #pragma unroll
    for (int n = 0; n < 8; n++) {
        int co = ty + 16 * n;
        #pragma unroll
        for (int m = 0; m < 8; m++) {
            int p = tx + 16 * m;
            size_t off = ((size_t)(b * CC) + co) * HWV + i0 + p;
            out[off] = fmaf(gamma, acc[n][m], x[off]);
        }
    }
}

// ---------------------------------------------------------------------------
extern "C" void kernel_launch(void* const* d_in, const int* in_sizes, int n_in,
                              void* d_out, int out_size)
{
    const float* x   = (const float*)d_in[0];
    const float* wth = (const float*)d_in[1];
    const float* wph = (const float*)d_in[2];
    const float* wg  = (const float*)d_in[3];
    const float* wo  = (const float*)d_in[4];
    const float* gmm = (const float*)d_in[5];
    float* out = (float*)d_out;

    const int SMEM_A = (128 * 128 + 128 * 97) * 4;            // 115200
    const int SMEM_B = (PJV * C8) * 4 + (PJV * 32) * 4;       // 196608
    const int SMEM_C = (128 * 65 + 64 * 129) * 4;             // 66304

    cudaFuncSetAttribute(convpool_kernel, cudaFuncAttributeMaxDynamicSharedMemorySize, SMEM_A);
    cudaFuncSetAttribute(attn_kernel,     cudaFuncAttributeMaxDynamicSharedMemorySize, SMEM_B);
    cudaFuncSetAttribute(epilogue_kernel, cudaFuncAttributeMaxDynamicSharedMemorySize, SMEM_C);

    convpool_kernel<<<256, 256, SMEM_A>>>(x, wth, wph, wg);
    attn_kernel<<<dim3(16, 8), 128, SMEM_B>>>();
    epilogue_kernel<<<dim3(32, 8), 256, SMEM_C>>>(x, wo, gmm, out);
}

// round 3
// speedup vs baseline: 2.5445x; 2.5445x over previous
#include <cuda_runtime.h>
#include <cuda_bf16.h>
#include <cstdint>

// Problem constants
#define BB    8
#define CC    128
#define HWV   4096       // H*W
#define PJV   1024       // pooled positions
#define C8    16
#define C2    64

// Scratch (device globals; no allocation allowed)
__device__ __align__(16) __nv_bfloat16  Qbf[BB * HWV * C8];   // 1 MB
__device__ __align__(16) __nv_bfloat16  Kbf[BB * PJV * C8];   // 256 KB
__device__ __align__(16) __nv_bfloat16  Vg [BB * PJV * C2];   // 1 MB
__device__ __align__(16) float          Og [BB * HWV * C2];   // 8 MB

// ===================== helpers =============================================
__device__ __forceinline__ uint32_t smem_u32(const void* p) {
    uint32_t a;
    asm("{ .reg .u64 t; cvta.to.shared.u64 t, %1; cvt.u32.u64 %0, t; }" : "=r"(a) : "l"(p));
    return a;
}
#define SWZ(o) ((o) ^ (((o) >> 3) & 0x70))

__device__ __forceinline__ void cp_async16(uint32_t dst, const void* src) {
    asm volatile("cp.async.cg.shared.global [%0], [%1], 16;" :: "r"(dst), "l"(src) : "memory");
}
#define CP_WAIT_ALL() asm volatile("cp.async.commit_group;\n\tcp.async.wait_group 0;" ::: "memory")

#define LDSM_X4(rr, addr) \
    asm volatile("ldmatrix.sync.aligned.m8n8.x4.shared.b16 {%0,%1,%2,%3}, [%4];" \
        : "=r"((rr)[0]), "=r"((rr)[1]), "=r"((rr)[2]), "=r"((rr)[3]) : "r"(addr))

#define LDSM_X4_T(rr, addr) \
    asm volatile("ldmatrix.sync.aligned.m8n8.x4.trans.shared.b16 {%0,%1,%2,%3}, [%4];" \
        : "=r"((rr)[0]), "=r"((rr)[1]), "=r"((rr)[2]), "=r"((rr)[3]) : "r"(addr))

#define MMA16816(d, a, b0, b1) \
    asm volatile("mma.sync.aligned.m16n8k16.row.col.f32.bf16.bf16.f32 " \
        "{%0,%1,%2,%3}, {%4,%5,%6,%7}, {%8,%9}, {%10,%11,%12,%13};" \
        : "=f"((d)[0]), "=f"((d)[1]), "=f"((d)[2]), "=f"((d)[3]) \
        : "r"((a)[0]), "r"((a)[1]), "r"((a)[2]), "r"((a)[3]), "r"(b0), "r"(b1), \
          "f"(0.0f), "f"(0.0f), "f"(0.0f), "f"(0.0f))

#define MMA16816_ACC(d, a, b0, b1) \
    asm volatile("mma.sync.aligned.m16n8k16.row.col.f32.bf16.bf16.f32 " \
        "{%0,%1,%2,%3}, {%4,%5,%6,%7}, {%8,%9}, {%0,%1,%2,%3};" \
        : "+f"((d)[0]), "+f"((d)[1]), "+f"((d)[2]), "+f"((d)[3]) \
        : "r"((a)[0]), "r"((a)[1]), "r"((a)[2]), "r"((a)[3]), "r"(b0), "r"(b1))

__device__ __forceinline__ uint32_t cvt_bf16x2(float hi, float lo) {
    uint32_t r;
    asm("cvt.rn.bf16x2.f32 %0, %1, %2;" : "=r"(r) : "f"(hi), "f"(lo));
    return r;
}

// ---------------------------------------------------------------------------
// Kernel A: fused 1x1 convs (theta/phi/g) + 2x2 maxpool for phi/g.
// grid 256 = (b, row-pair), 256 threads. x streamed in 64-channel chunks so
// smem = 82.4KB -> 2 CTAs/SM. Emits Q/K in bf16 for the HMMA attention.
// ---------------------------------------------------------------------------
__global__ __launch_bounds__(256) void convpool_kernel(
    const float* __restrict__ x,
    const float* __restrict__ wth,
    const float* __restrict__ wph,
    const float* __restrict__ wg)
{
    extern __shared__ float sm[];
    float* xs = sm;              // 64*128
    float* wT = sm + 64 * 128;   // 128*97 (pbuf overlays after GEMM)

    const int b  = blockIdx.x >> 5;
    const int ph = blockIdx.x & 31;
    const int tid = threadIdx.x;

    for (int idx = tid; idx < 96 * 128; idx += 256) {
        int oc = idx >> 7, c = idx & 127;
        float v;
        if (oc < 16)      v = wth[oc * 128 + c];
        else if (oc < 32) v = wph[(oc - 16) * 128 + c];
        else              v = wg[(oc - 32) * 128 + c];
        wT[c * 97 + oc] = v;
    }

    const float* xbase = x + (size_t)b * (CC * HWV) + ph * 128;
    const int ty = tid >> 4, tx = tid & 15;
    float acc[6][8];
    #pragma unroll
    for (int n = 0; n < 6; n++)
        #pragma unroll
        for (int m = 0; m < 8; m++) acc[n][m] = 0.0f;

    for (int half = 0; half < 2; half++) {
        __syncthreads();
        for (int idx = tid; idx < 64 * 128; idx += 256) {
            int c = idx >> 7, p = idx & 127;
            xs[idx] = xbase[(size_t)(half * 64 + c) * HWV + p];
        }
        __syncthreads();
        #pragma unroll 4
        for (int c = 0; c < 64; c++) {
            float xv[8], wv[6];
            #pragma unroll
            for (int m = 0; m < 8; m++) xv[m] = xs[c * 128 + tx + 16 * m];
            #pragma unroll
            for (int n = 0; n < 6; n++) wv[n] = wT[(half * 64 + c) * 97 + ty + 16 * n];
            #pragma unroll
            for (int n = 0; n < 6; n++)
                #pragma unroll
                for (int m = 0; m < 8; m++)
                    acc[n][m] = fmaf(wv[n], xv[m], acc[n][m]);
        }
    }

    // theta -> Qbf (bf16)
    #pragma unroll
    for (int m = 0; m < 8; m++) {
        int p = tx + 16 * m;
        Qbf[((size_t)(b * HWV) + ph * 128 + p) * C8 + ty] = __float2bfloat16(acc[0][m]);
    }

    __syncthreads();
    float* pbuf = wT;  // [80 rows][128 pos], weights dead
    #pragma unroll
    for (int n = 1; n < 6; n++) {
        int row = (n - 1) * 16 + ty;
        #pragma unroll
        for (int m = 0; m < 8; m++)
            pbuf[row * 128 + tx + 16 * m] = acc[n][m];
    }
    __syncthreads();

    for (int idx = tid; idx < 80 * 32; idx += 256) {
        int cc = idx >> 5, pw = idx & 31;
        int p0 = 2 * pw;
        float v0 = pbuf[cc * 128 + p0];
        float v1 = pbuf[cc * 128 + p0 + 1];
        float v2 = pbuf[cc * 128 + 64 + p0];
        float v3 = pbuf[cc * 128 + 64 + p0 + 1];
        float v = fmaxf(fmaxf(v0, v1), fmaxf(v2, v3));
        int pj = ph * 32 + pw;
        if (cc < 16)
            Kbf[((size_t)(b * PJV) + pj) * C8 + cc] = __float2bfloat16(v);
        else
            Vg[((size_t)(b * PJV) + pj) * C2 + (cc - 16)] = __float2bfloat16(v);
    }
}

// ---------------------------------------------------------------------------
// Kernel B: HMMA flash attention. 1 CTA per (b, 128-query tile), 128 threads.
// Q(4KB) + K(32KB) + V(128KB) resident in smem (XOR-swizzled, conflict-free
// ldmatrix). Each warp owns 32 queries (2 x m16 tiles). Max-free softmax.
// S-fragment -> P A-fragment via cvt.bf16x2 (FA2 layout identity).
// ---------------------------------------------------------------------------
#define QOFF  0u
#define KOFF  4096u
#define VOFF  36864u

__global__ __launch_bounds__(128, 1) void attn_kernel()
{
    extern __shared__ char smc[];
    const uint32_t sb = smem_u32(smc);
    const int tid = threadIdx.x, wid = tid >> 5, lid = tid & 31;
    const int b = blockIdx.y, m0 = blockIdx.x * 128;

    // ---- async loads of Q/K/V into smem ----
    {
        const char* qsrc = (const char*)(Qbf + ((size_t)(b * HWV) + m0) * C8);
        int m = tid;  // 0..127
        cp_async16(sb + QOFF + SWZ(m * 32),      qsrc + m * 32);
        cp_async16(sb + QOFF + SWZ(m * 32 + 16), qsrc + m * 32 + 16);

        const char* ksrc = (const char*)(Kbf + (size_t)b * PJV * C8);
        #pragma unroll
        for (int j = tid; j < PJV; j += 128) {
            cp_async16(sb + KOFF + SWZ(j * 32),      ksrc + j * 32);
            cp_async16(sb + KOFF + SWZ(j * 32 + 16), ksrc + j * 32 + 16);
        }
        const char* vsrc = (const char*)(Vg + (size_t)b * PJV * C2);
        #pragma unroll
        for (int idx = tid; idx < PJV * 8; idx += 128)
            cp_async16(sb + VOFF + SWZ(idx * 16), vsrc + idx * 16);
        CP_WAIT_ALL();
    }
    __syncthreads();

    // ldmatrix lane addressing
    const int t  = lid >> 3, r = lid & 7;
    const int rowsel = (t & 1) * 8 + r;   // row within 16-row tile
    const int khalf  = (t >> 1) * 16;     // byte offset of k-half (for 32B rows)

    // Q fragments: 2 m-tiles per warp
    uint32_t qa[4], qb[4];
    LDSM_X4(qa, sb + QOFF + SWZ((uint32_t)((wid * 32 + rowsel) * 32 + khalf)));
    LDSM_X4(qb, sb + QOFF + SWZ((uint32_t)((wid * 32 + 16 + rowsel) * 32 + khalf)));

    float oacc[2][8][4];
    #pragma unroll
    for (int mt = 0; mt < 2; mt++)
        #pragma unroll
        for (int nt = 0; nt < 8; nt++)
            #pragma unroll
            for (int e = 0; e < 4; e++) oacc[mt][nt][e] = 0.0f;
    float lsum[2][2] = {{0.0f, 0.0f}, {0.0f, 0.0f}};

    const uint32_t kladdr_base = (uint32_t)(rowsel * 32 + khalf);
    const uint32_t vladdr_row  = (uint32_t)((t & 1) * 8 + r) * 128 + (uint32_t)((t >> 1) * 8) * 2;

    #pragma unroll 1
    for (int jt = 0; jt < 64; jt++) {
        const uint32_t j0 = (uint32_t)jt * 16;
        // K fragments for 16 j
        uint32_t kb[4];
        LDSM_X4(kb, sb + KOFF + SWZ(kladdr_base + j0 * 32));

        // S = Q @ K^T  (two m-tiles x two n-tiles)
        float sA0[4], sA1[4], sB0[4], sB1[4];
        MMA16816(sA0, qa, kb[0], kb[2]);
        MMA16816(sA1, qa, kb[1], kb[3]);
        MMA16816(sB0, qb, kb[0], kb[2]);
        MMA16816(sB1, qb, kb[1], kb[3]);

        // max-free softmax numerators + packing into P A-fragments
        uint32_t pA[4], pB[4];
        {
            float e0 = __expf(sA0[0]), e1 = __expf(sA0[1]), e2 = __expf(sA0[2]), e3 = __expf(sA0[3]);
            float f0 = __expf(sA1[0]), f1 = __expf(sA1[1]), f2 = __expf(sA1[2]), f3 = __expf(sA1[3]);
            lsum[0][0] += e0 + e1 + f0 + f1;
            lsum[0][1] += e2 + e3 + f2 + f3;
            pA[0] = cvt_bf16x2(e1, e0); pA[1] = cvt_bf16x2(e3, e2);
            pA[2] = cvt_bf16x2(f1, f0); pA[3] = cvt_bf16x2(f3, f2);
        }
        {
            float e0 = __expf(sB0[0]), e1 = __expf(sB0[1]), e2 = __expf(sB0[2]), e3 = __expf(sB0[3]);
            float f0 = __expf(sB1[0]), f1 = __expf(sB1[1]), f2 = __expf(sB1[2]), f3 = __expf(sB1[3]);
            lsum[1][0] += e0 + e1 + f0 + f1;
            lsum[1][1] += e2 + e3 + f2 + f3;
            pB[0] = cvt_bf16x2(e1, e0); pB[1] = cvt_bf16x2(e3, e2);
            pB[2] = cvt_bf16x2(f1, f0); pB[3] = cvt_bf16x2(f3, f2);
        }

        // O += P @ V  (V fragments via ldmatrix.trans)
        #pragma unroll
        for (int cq = 0; cq < 4; cq++) {
            uint32_t vb[4];
            LDSM_X4_T(vb, sb + VOFF + SWZ(vladdr_row + j0 * 128 + (uint32_t)cq * 32));
            MMA16816_ACC(oacc[0][2 * cq],     pA, vb[0], vb[1]);
            MMA16816_ACC(oacc[0][2 * cq + 1], pA, vb[2], vb[3]);
            MMA16816_ACC(oacc[1][2 * cq],     pB, vb[0], vb[1]);
            MMA16816_ACC(oacc[1][2 * cq + 1], pB, vb[2], vb[3]);
        }
    }

    // reduce row sums within quads (lanes g*4..g*4+3 share a row)
    #pragma unroll
    for (int mt = 0; mt < 2; mt++)
        #pragma unroll
        for (int hh = 0; hh < 2; hh++) {
            float l = lsum[mt][hh];
            l += __shfl_xor_sync(0xffffffffu, l, 1);
            l += __shfl_xor_sync(0xffffffffu, l, 2);
            lsum[mt][hh] = 1.0f / l;
        }

    const int g = lid >> 2, tc = lid & 3;
    #pragma unroll
    for (int mt = 0; mt < 2; mt++) {
        int mrow = m0 + wid * 32 + mt * 16 + g;
        float* o0 = Og + ((size_t)(b * HWV) + mrow) * C2;
        float* o1 = o0 + 8 * C2;
        #pragma unroll
        for (int nt = 0; nt < 8; nt++) {
            float2 w0, w1;
            w0.x = oacc[mt][nt][0] * lsum[mt][0];
            w0.y = oacc[mt][nt][1] * lsum[mt][0];
            w1.x = oacc[mt][nt][2] * lsum[mt][1];
            w1.y = oacc[mt][nt][3] * lsum[mt][1];
            *(float2*)(o0 + nt * 8 + tc * 2) = w0;
            *(float2*)(o1 + nt * 8 + tc * 2) = w1;
        }
    }
}

// ---------------------------------------------------------------------------
// Kernel C: out = x + gamma * (w_o @ o).   grid (32 itiles, 8 b), 256 thr.
// ---------------------------------------------------------------------------
__global__ __launch_bounds__(256) void epilogue_kernel(
    const float* __restrict__ x,
    const float* __restrict__ wo,
    const float* __restrict__ gptr,
    float* __restrict__ out)
{
    extern __shared__ float sm[];
    float* osm = sm;                 // [128][65]
    float* wT  = sm + 128 * 65;      // [64][129]

    const int it = blockIdx.x, b = blockIdx.y;
    const int i0 = it * 128;
    const int tid = threadIdx.x;

    for (int idx = tid; idx < 128 * 64; idx += 256) {
        int p = idx >> 6, c = idx & 63;
        osm[p * 65 + c] = Og[((size_t)(b * HWV) + i0 + p) * C2 + c];
    }
    for (int idx = tid; idx < 128 * 64; idx += 256) {
        int co = idx >> 6, c = idx & 63;
        wT[c * 129 + co] = wo[idx];
    }
    __syncthreads();

    const int ty = tid >> 4, tx = tid & 15;
    float acc[8][8];
    #pragma unroll
    for (int n = 0; n < 8; n++)
        #pragma unroll
        for (int m = 0; m < 8; m++) acc[n][m] = 0.0f;

    #pragma unroll 4
    for (int c = 0; c < 64; c++) {
        float wv[8], ov[8];
        #pragma unroll
        for (int n = 0; n < 8; n++) wv[n] = wT[c * 129 + ty + 16 * n];
        #pragma unroll
        for (int m = 0; m < 8; m++) ov[m] = osm[(tx + 16 * m) * 65 + c];
        #pragma unroll
        for (int n = 0; n < 8; n++)
            #pragma unroll
            for (int m = 0; m < 8; m++)
                acc[n][m] = fmaf(wv[n], ov[m], acc[n][m]);
    }

    const float gamma = __ldg(gptr);
    #pragma unroll
    for (int n = 0; n < 8; n++) {
        int co = ty + 16 * n;
        #pragma unroll
        for (int m = 0; m < 8; m++) {
            int p = tx + 16 * m;
            size_t off = ((size_t)(b * CC) + co) * HWV + i0 + p;
            out[off] = fmaf(gamma, acc[n][m], x[off]);
        }
    }
}

// ---------------------------------------------------------------------------
extern "C" void kernel_launch(void* const* d_in, const int* in_sizes, int n_in,
                              void* d_out, int out_size)
{
    const float* x   = (const float*)d_in[0];
    const float* wth = (const float*)d_in[1];
    const float* wph = (const float*)d_in[2];
    const float* wg  = (const float*)d_in[3];
    const float* wo  = (const float*)d_in[4];
    const float* gmm = (const float*)d_in[5];
    float* out = (float*)d_out;

    const int SMEM_A = (64 * 128 + 128 * 97) * 4;   // 82432
    const int SMEM_B = 4096 + 32768 + 131072;       // 167936
    const int SMEM_C = (128 * 65 + 64 * 129) * 4;   // 66304

    cudaFuncSetAttribute(convpool_kernel, cudaFuncAttributeMaxDynamicSharedMemorySize, SMEM_A);
    cudaFuncSetAttribute(attn_kernel,     cudaFuncAttributeMaxDynamicSharedMemorySize, SMEM_B);
    cudaFuncSetAttribute(epilogue_kernel, cudaFuncAttributeMaxDynamicSharedMemorySize, SMEM_C);

    convpool_kernel<<<256, 256, SMEM_A>>>(x, wth, wph, wg);
    attn_kernel<<<dim3(32, 8), 128, SMEM_B>>>();
    epilogue_kernel<<<dim3(32, 8), 256, SMEM_C>>>(x, wo, gmm, out);
}

// round 5
// speedup vs baseline: 3.7712x; 1.4821x over previous
#include <cuda_runtime.h>
#include <cuda_bf16.h>
#include <cstdint>

// Problem constants
#define BB    8
#define CC    128
#define HWV   4096       // H*W
#define PJV   1024       // pooled positions
#define C8    16
#define C2    64

// Scratch (device globals; no allocation allowed)
__device__ __align__(16) __nv_bfloat16  Qbf[BB * HWV * C8];   // 1 MB
__device__ __align__(16) __nv_bfloat16  Kbf[BB * PJV * C8];   // 256 KB
__device__ __align__(16) __nv_bfloat16  Vg [BB * PJV * C2];   // 1 MB
__device__ __align__(16) __nv_bfloat16  Og [BB * HWV * C2];   // 4 MB (normalized attn out, bf16)

// ===================== helpers =============================================
__device__ __forceinline__ uint32_t smem_u32(const void* p) {
    uint32_t a;
    asm("{ .reg .u64 t; cvta.to.shared.u64 t, %1; cvt.u32.u64 %0, t; }" : "=r"(a) : "l"(p));
    return a;
}
#define SWZ(o) ((o) ^ (((o) >> 3) & 0x70))

__device__ __forceinline__ void cp_async16(uint32_t dst, const void* src) {
    asm volatile("cp.async.cg.shared.global [%0], [%1], 16;" :: "r"(dst), "l"(src) : "memory");
}
#define CP_WAIT_ALL() asm volatile("cp.async.commit_group;\n\tcp.async.wait_group 0;" ::: "memory")

#define LDSM_X4(rr, addr) \
    asm volatile("ldmatrix.sync.aligned.m8n8.x4.shared.b16 {%0,%1,%2,%3}, [%4];" \
        : "=r"((rr)[0]), "=r"((rr)[1]), "=r"((rr)[2]), "=r"((rr)[3]) : "r"(addr))

#define LDSM_X4_T(rr, addr) \
    asm volatile("ldmatrix.sync.aligned.m8n8.x4.trans.shared.b16 {%0,%1,%2,%3}, [%4];" \
        : "=r"((rr)[0]), "=r"((rr)[1]), "=r"((rr)[2]), "=r"((rr)[3]) : "r"(addr))

#define MMA16816(d, a, b0, b1) \
    asm volatile("mma.sync.aligned.m16n8k16.row.col.f32.bf16.bf16.f32 " \
        "{%0,%1,%2,%3}, {%4,%5,%6,%7}, {%8,%9}, {%10,%11,%12,%13};" \
        : "=f"((d)[0]), "=f"((d)[1]), "=f"((d)[2]), "=f"((d)[3]) \
        : "r"((a)[0]), "r"((a)[1]), "r"((a)[2]), "r"((a)[3]), "r"(b0), "r"(b1), \
          "f"(0.0f), "f"(0.0f), "f"(0.0f), "f"(0.0f))

#define MMA16816_ACC(d, a, b0, b1) \
    asm volatile("mma.sync.aligned.m16n8k16.row.col.f32.bf16.bf16.f32 " \
        "{%0,%1,%2,%3}, {%4,%5,%6,%7}, {%8,%9}, {%0,%1,%2,%3};" \
        : "+f"((d)[0]), "+f"((d)[1]), "+f"((d)[2]), "+f"((d)[3]) \
        : "r"((a)[0]), "r"((a)[1]), "r"((a)[2]), "r"((a)[3]), "r"(b0), "r"(b1))

__device__ __forceinline__ uint32_t cvt_bf16x2(float hi, float lo) {
    uint32_t r;
    asm("cvt.rn.bf16x2.f32 %0, %1, %2;" : "=r"(r) : "f"(hi), "f"(lo));
    return r;
}

// ---------------------------------------------------------------------------
// Kernel A: fused 1x1 convs (theta/phi/g) + 2x2 maxpool via bf16 HMMA.
// grid 256 = (b, row-pair ph), 256 threads. smem 56KB -> 3 CTAs/SM.
// W[96 oc][128 c] staged as two c-half blocks; x[128 c][128 pos] staged as
// two POSITION-half blocks (each holds all 128 c rows).
// ---------------------------------------------------------------------------
#define CP_WOFF  0u          // [h:2][oc:96][128B]  = 24576
#define CP_XOFF  24576u      // [ph:2][c:128][128B] = 32768
#define CP_ABUF  24576u      // overlays x: [96][272B] = 26112
#define CP_SMEM  57344

__global__ __launch_bounds__(256) void convpool_kernel(
    const float* __restrict__ x,
    const float* __restrict__ wth,
    const float* __restrict__ wph,
    const float* __restrict__ wg)
{
    extern __shared__ char smc[];
    const uint32_t sb = smem_u32(smc);
    const int b  = blockIdx.x >> 5;
    const int ph = blockIdx.x & 31;
    const int tid = threadIdx.x, wid = tid >> 5, lid = tid & 31;

    // ---- stage W (96x128 fp32 -> bf16, swizzled c-halves) ----
    for (int idx = tid; idx < 96 * 32; idx += 256) {
        int oc = idx >> 5, c4 = idx & 31;
        const float4* wsrc;
        if (oc < 16)      wsrc = (const float4*)(wth + oc * 128) + c4;
        else if (oc < 32) wsrc = (const float4*)(wph + (oc - 16) * 128) + c4;
        else              wsrc = (const float4*)(wg  + (oc - 32) * 128) + c4;
        float4 v = *wsrc;
        uint2 pk;
        pk.x = cvt_bf16x2(v.y, v.x);
        pk.y = cvt_bf16x2(v.w, v.z);
        int c = c4 * 4, h = c >> 6, cin = c & 63;
        uint32_t off = (uint32_t)(oc * 128 + cin * 2);
        *(uint2*)(smc + CP_WOFF + h * 12288 + SWZ(off)) = pk;
    }
    // ---- stage x tile (128c x 128pos fp32 -> bf16, swizzled pos-halves) ----
    const float* xbase = x + (size_t)b * (CC * HWV) + ph * 128;
    for (int idx = tid; idx < 128 * 32; idx += 256) {
        int c = idx >> 5, p4 = idx & 31;
        float4 v = *((const float4*)(xbase + (size_t)c * HWV) + p4);
        uint2 pk;
        pk.x = cvt_bf16x2(v.y, v.x);
        pk.y = cvt_bf16x2(v.w, v.z);
        int p = p4 * 4, h = p >> 6, pin = p & 63;
        uint32_t off = (uint32_t)(c * 128 + pin * 2);
        *(uint2*)(smc + CP_XOFF + h * 16384 + SWZ(off)) = pk;
    }
    __syncthreads();

    // ---- MMA: warp w -> pos group w*16 ----
    const int t = lid >> 3, r = lid & 7;
    const int rowsel = (t & 1) * 8 + r;
    const int khalf16 = (t >> 1) * 16;
    const int pg = wid * 16;
    const int xh = pg >> 6;
    const int pin = pg & 63;

    float acc[6][2][4];
    #pragma unroll
    for (int mt = 0; mt < 6; mt++)
        #pragma unroll
        for (int nt = 0; nt < 2; nt++)
            #pragma unroll
            for (int e = 0; e < 4; e++) acc[mt][nt][e] = 0.0f;

    #pragma unroll 2
    for (int ks = 0; ks < 8; ks++) {
        const int hk = ks >> 2, cq = ks & 3;
        uint32_t bfr[4];
        // x rows are the FULL c range (0..127) within each position-half block:
        // row = ks*16 + (t&1)*8 + r   (bug fix vs R4: was cq*16)
        LDSM_X4_T(bfr, sb + CP_XOFF + xh * 16384 +
                  SWZ((uint32_t)((ks * 16 + (t & 1) * 8 + r) * 128 + pin * 2 + (t >> 1) * 16)));
        #pragma unroll
        for (int mt = 0; mt < 6; mt++) {
            uint32_t a[4];
            LDSM_X4(a, sb + CP_WOFF + hk * 12288 +
                    SWZ((uint32_t)((mt * 16 + rowsel) * 128 + cq * 32 + khalf16)));
            MMA16816_ACC(acc[mt][0], a, bfr[0], bfr[1]);
            MMA16816_ACC(acc[mt][1], a, bfr[2], bfr[3]);
        }
    }
    __syncthreads();   // all warps done reading x before ABUF overlay write

    // ---- accum -> smem bf16 buffer [96 oc][272B stride] ----
    const int g = lid >> 2, tc = lid & 3;
    #pragma unroll
    for (int mt = 0; mt < 6; mt++)
        #pragma unroll
        for (int nt = 0; nt < 2; nt++) {
            uint32_t lo = cvt_bf16x2(acc[mt][nt][1], acc[mt][nt][0]);
            uint32_t hi = cvt_bf16x2(acc[mt][nt][3], acc[mt][nt][2]);
            uint32_t colb = (uint32_t)(pg + nt * 8 + tc * 2) * 2;
            *(uint32_t*)(smc + CP_ABUF + (mt * 16 + g)     * 272 + colb) = lo;
            *(uint32_t*)(smc + CP_ABUF + (mt * 16 + 8 + g) * 272 + colb) = hi;
        }
    __syncthreads();

    // ---- theta (oc 0..15) -> Qbf ----
    for (int idx = tid; idx < 2048; idx += 256) {
        int p = idx >> 4, oc = idx & 15;
        __nv_bfloat16 v = *(const __nv_bfloat16*)(smc + CP_ABUF + oc * 272 + p * 2);
        Qbf[((size_t)(b * HWV) + ph * 128 + p) * C8 + oc] = v;
    }
    // ---- pool phi/g (oc 16..95): rows p and p+64 = byte +128 ----
    for (int idx = tid; idx < 80 * 32; idx += 256) {
        int cc = idx >> 5, pw = idx & 31;
        const char* rowp = smc + CP_ABUF + (16 + cc) * 272;
        float v0 = __bfloat162float(*(const __nv_bfloat16*)(rowp + 4 * pw));
        float v1 = __bfloat162float(*(const __nv_bfloat16*)(rowp + 4 * pw + 2));
        float v2 = __bfloat162float(*(const __nv_bfloat16*)(rowp + 128 + 4 * pw));
        float v3 = __bfloat162float(*(const __nv_bfloat16*)(rowp + 128 + 4 * pw + 2));
        float m = fmaxf(fmaxf(v0, v1), fmaxf(v2, v3));
        int pj = ph * 32 + pw;
        if (cc < 16)
            Kbf[((size_t)(b * PJV) + pj) * C8 + cc] = __float2bfloat16(m);
        else
            Vg[((size_t)(b * PJV) + pj) * C2 + (cc - 16)] = __float2bfloat16(m);
    }
}

// ---------------------------------------------------------------------------
// Kernel B: HMMA flash attention. 1 CTA per (b, 256-query tile), 256 threads.
// Single wave (128 CTAs). Q(8KB)+K(32KB)+V(128KB) smem. Max-free softmax.
// ---------------------------------------------------------------------------
#define QOFF  0u
#define KOFF  8192u
#define VOFF  40960u

__global__ __launch_bounds__(256, 1) void attn_kernel()
{
    extern __shared__ char smc[];
    const uint32_t sb = smem_u32(smc);
    const int tid = threadIdx.x, wid = tid >> 5, lid = tid & 31;
    const int b = blockIdx.y, m0 = blockIdx.x * 256;

    // ---- async loads of Q/K/V into smem ----
    {
        const char* qsrc = (const char*)(Qbf + ((size_t)(b * HWV) + m0) * C8);
        int m = tid;  // 0..255
        cp_async16(sb + QOFF + SWZ(m * 32),      qsrc + m * 32);
        cp_async16(sb + QOFF + SWZ(m * 32 + 16), qsrc + m * 32 + 16);

        const char* ksrc = (const char*)(Kbf + (size_t)b * PJV * C8);
        #pragma unroll
        for (int j = tid; j < PJV; j += 256) {
            cp_async16(sb + KOFF + SWZ(j * 32),      ksrc + j * 32);
            cp_async16(sb + KOFF + SWZ(j * 32 + 16), ksrc + j * 32 + 16);
        }
        const char* vsrc = (const char*)(Vg + (size_t)b * PJV * C2);
        #pragma unroll
        for (int idx = tid; idx < PJV * 8; idx += 256)
            cp_async16(sb + VOFF + SWZ(idx * 16), vsrc + idx * 16);
        CP_WAIT_ALL();
    }
    __syncthreads();

    const int t  = lid >> 3, r = lid & 7;
    const int rowsel = (t & 1) * 8 + r;
    const int khalf  = (t >> 1) * 16;

    uint32_t qa[4], qb[4];
    LDSM_X4(qa, sb + QOFF + SWZ((uint32_t)((wid * 32 + rowsel) * 32 + khalf)));
    LDSM_X4(qb, sb + QOFF + SWZ((uint32_t)((wid * 32 + 16 + rowsel) * 32 + khalf)));

    float oacc[2][8][4];
    #pragma unroll
    for (int mt = 0; mt < 2; mt++)
        #pragma unroll
        for (int nt = 0; nt < 8; nt++)
            #pragma unroll
            for (int e = 0; e < 4; e++) oacc[mt][nt][e] = 0.0f;
    float lsum[2][2] = {{0.0f, 0.0f}, {0.0f, 0.0f}};

    const uint32_t kladdr_base = (uint32_t)(rowsel * 32 + khalf);
    const uint32_t vladdr_row  = (uint32_t)((t & 1) * 8 + r) * 128 + (uint32_t)((t >> 1) * 8) * 2;

    #pragma unroll 1
    for (int jt = 0; jt < 64; jt++) {
        const uint32_t j0 = (uint32_t)jt * 16;
        uint32_t kb[4];
        LDSM_X4(kb, sb + KOFF + SWZ(kladdr_base + j0 * 32));

        float sA0[4], sA1[4], sB0[4], sB1[4];
        MMA16816(sA0, qa, kb[0], kb[2]);
        MMA16816(sA1, qa, kb[1], kb[3]);
        MMA16816(sB0, qb, kb[0], kb[2]);
        MMA16816(sB1, qb, kb[1], kb[3]);

        uint32_t pA[4], pB[4];
        {
            float e0 = __expf(sA0[0]), e1 = __expf(sA0[1]), e2 = __expf(sA0[2]), e3 = __expf(sA0[3]);
            float f0 = __expf(sA1[0]), f1 = __expf(sA1[1]), f2 = __expf(sA1[2]), f3 = __expf(sA1[3]);
            lsum[0][0] += e0 + e1 + f0 + f1;
            lsum[0][1] += e2 + e3 + f2 + f3;
            pA[0] = cvt_bf16x2(e1, e0); pA[1] = cvt_bf16x2(e3, e2);
            pA[2] = cvt_bf16x2(f1, f0); pA[3] = cvt_bf16x2(f3, f2);
        }
        {
            float e0 = __expf(sB0[0]), e1 = __expf(sB0[1]), e2 = __expf(sB0[2]), e3 = __expf(sB0[3]);
            float f0 = __expf(sB1[0]), f1 = __expf(sB1[1]), f2 = __expf(sB1[2]), f3 = __expf(sB1[3]);
            lsum[1][0] += e0 + e1 + f0 + f1;
            lsum[1][1] += e2 + e3 + f2 + f3;
            pB[0] = cvt_bf16x2(e1, e0); pB[1] = cvt_bf16x2(e3, e2);
            pB[2] = cvt_bf16x2(f1, f0); pB[3] = cvt_bf16x2(f3, f2);
        }

        #pragma unroll
        for (int cq = 0; cq < 4; cq++) {
            uint32_t vb[4];
            LDSM_X4_T(vb, sb + VOFF + SWZ(vladdr_row + j0 * 128 + (uint32_t)cq * 32));
            MMA16816_ACC(oacc[0][2 * cq],     pA, vb[0], vb[1]);
            MMA16816_ACC(oacc[0][2 * cq + 1], pA, vb[2], vb[3]);
            MMA16816_ACC(oacc[1][2 * cq],     pB, vb[0], vb[1]);
            MMA16816_ACC(oacc[1][2 * cq + 1], pB, vb[2], vb[3]);
        }
    }

    #pragma unroll
    for (int mt = 0; mt < 2; mt++)
        #pragma unroll
        for (int hh = 0; hh < 2; hh++) {
            float l = lsum[mt][hh];
            l += __shfl_xor_sync(0xffffffffu, l, 1);
            l += __shfl_xor_sync(0xffffffffu, l, 2);
            lsum[mt][hh] = 1.0f / l;
        }

    const int g = lid >> 2, tc = lid & 3;
    #pragma unroll
    for (int mt = 0; mt < 2; mt++) {
        int mrow = m0 + wid * 32 + mt * 16 + g;
        __nv_bfloat16* o0 = Og + ((size_t)(b * HWV) + mrow) * C2;
        __nv_bfloat16* o1 = o0 + 8 * C2;
        #pragma unroll
        for (int nt = 0; nt < 8; nt++) {
            uint32_t w0 = cvt_bf16x2(oacc[mt][nt][1] * lsum[mt][0],
                                     oacc[mt][nt][0] * lsum[mt][0]);
            uint32_t w1 = cvt_bf16x2(oacc[mt][nt][3] * lsum[mt][1],
                                     oacc[mt][nt][2] * lsum[mt][1]);
            *(uint32_t*)(o0 + nt * 8 + tc * 2) = w0;
            *(uint32_t*)(o1 + nt * 8 + tc * 2) = w1;
        }
    }
}

// ---------------------------------------------------------------------------
// Kernel C: out = x + gamma * (w_o @ o).   grid (32 itiles, 8 b), 256 thr.
// ---------------------------------------------------------------------------
__global__ __launch_bounds__(256) void epilogue_kernel(
    const float* __restrict__ x,
    const float* __restrict__ wo,
    const float* __restrict__ gptr,
    float* __restrict__ out)
{
    extern __shared__ float sm[];
    float* osm = sm;                 // [128][65]
    float* wT  = sm + 128 * 65;      // [64][129]

    const int it = blockIdx.x, b = blockIdx.y;
    const int i0 = it * 128;
    const int tid = threadIdx.x;

    // stage o (bf16 -> f32), vectorized: 1024 uint4 = 8 bf16 each
    for (int idx = tid; idx < 1024; idx += 256) {
        int p = idx >> 3, chunk = idx & 7;
        uint4 v = ((const uint4*)(Og + ((size_t)(b * HWV) + i0 + p) * C2))[chunk];
        float* dst = osm + p * 65 + chunk * 8;
        float2 f0 = __bfloat1622float2(*(__nv_bfloat162*)&v.x);
        float2 f1 = __bfloat1622float2(*(__nv_bfloat162*)&v.y);
        float2 f2 = __bfloat1622float2(*(__nv_bfloat162*)&v.z);
        float2 f3 = __bfloat1622float2(*(__nv_bfloat162*)&v.w);
        dst[0] = f0.x; dst[1] = f0.y; dst[2] = f1.x; dst[3] = f1.y;
        dst[4] = f2.x; dst[5] = f2.y; dst[6] = f3.x; dst[7] = f3.y;
    }
    for (int idx = tid; idx < 128 * 64; idx += 256) {
        int co = idx >> 6, c = idx & 63;
        wT[c * 129 + co] = wo[idx];
    }
    __syncthreads();

    const int ty = tid >> 4, tx = tid & 15;
    float acc[8][8];
    #pragma unroll
    for (int n = 0; n < 8; n++)
        #pragma unroll
        for (int m = 0; m < 8; m++) acc[n][m] = 0.0f;

    #pragma unroll 4
    for (int c = 0; c < 64; c++) {
        float wv[8], ov[8];
        #pragma unroll
        for (int n = 0; n < 8; n++) wv[n] = wT[c * 129 + ty + 16 * n];
        #pragma unroll
        for (int m = 0; m < 8; m++) ov[m] = osm[(tx + 16 * m) * 65 + c];
        #pragma unroll
        for (int n = 0; n < 8; n++)
            #pragma unroll
            for (int m = 0; m < 8; m++)
                acc[n][m] = fmaf(wv[n], ov[m], acc[n][m]);
    }

    const float gamma = __ldg(gptr);
    #pragma unroll
    for (int n = 0; n < 8; n++) {
        int co = ty + 16 * n;
        #pragma unroll
        for (int m = 0; m < 8; m++) {
            int p = tx + 16 * m;
            size_t off = ((size_t)(b * CC) + co) * HWV + i0 + p;
            out[off] = fmaf(gamma, acc[n][m], x[off]);
        }
    }
}

// ---------------------------------------------------------------------------
extern "C" void kernel_launch(void* const* d_in, const int* in_sizes, int n_in,
                              void* d_out, int out_size)
{
    const float* x   = (const float*)d_in[0];
    const float* wth = (const float*)d_in[1];
    const float* wph = (const float*)d_in[2];
    const float* wg  = (const float*)d_in[3];
    const float* wo  = (const float*)d_in[4];
    const float* gmm = (const float*)d_in[5];
    float* out = (float*)d_out;

    const int SMEM_A = CP_SMEM;                    // 57344
    const int SMEM_B = 8192 + 32768 + 131072;      // 172032
    const int SMEM_C = (128 * 65 + 64 * 129) * 4;  // 66304

    cudaFuncSetAttribute(convpool_kernel, cudaFuncAttributeMaxDynamicSharedMemorySize, SMEM_A);
    cudaFuncSetAttribute(attn_kernel,     cudaFuncAttributeMaxDynamicSharedMemorySize, SMEM_B);
    cudaFuncSetAttribute(epilogue_kernel, cudaFuncAttributeMaxDynamicSharedMemorySize, SMEM_C);

    convpool_kernel<<<256, 256, SMEM_A>>>(x, wth, wph, wg);
    attn_kernel<<<dim3(16, 8), 256, SMEM_B>>>();
    epilogue_kernel<<<dim3(32, 8), 256, SMEM_C>>>(x, wo, gmm, out);
}

// round 6
// speedup vs baseline: 5.1844x; 1.3747x over previous
#include <cuda_runtime.h>
#include <cuda_bf16.h>
#include <cuda_fp16.h>
#include <cstdint>

// Problem constants
#define BB    8
#define CC    128
#define HWV   4096       // H*W
#define PJV   1024       // pooled positions
#define C8    16
#define C2    64
#define LG2E  1.44269504f

// Scratch (device globals; no allocation allowed)
__device__ __align__(16) __half         Qf [BB * HWV * C8];   // 1 MB   (pre-scaled by log2e)
__device__ __align__(16) __half         Kf [BB * PJV * C8];   // 256 KB
__device__ __align__(16) __nv_bfloat16  Vg [BB * PJV * C2];   // 1 MB   (bf16: pairs with bf16 P)
__device__ __align__(16) __half         Og [BB * HWV * C2];   // 4 MB   (normalized attn out)

// ===================== helpers =============================================
__device__ __forceinline__ uint32_t smem_u32(const void* p) {
    uint32_t a;
    asm("{ .reg .u64 t; cvta.to.shared.u64 t, %1; cvt.u32.u64 %0, t; }" : "=r"(a) : "l"(p));
    return a;
}
#define SWZ(o) ((o) ^ (((o) >> 3) & 0x70))

__device__ __forceinline__ void cp_async16(uint32_t dst, const void* src) {
    asm volatile("cp.async.cg.shared.global [%0], [%1], 16;" :: "r"(dst), "l"(src) : "memory");
}
#define CP_WAIT_ALL() asm volatile("cp.async.commit_group;\n\tcp.async.wait_group 0;" ::: "memory")

#define LDSM_X4(rr, addr) \
    asm volatile("ldmatrix.sync.aligned.m8n8.x4.shared.b16 {%0,%1,%2,%3}, [%4];" \
        : "=r"((rr)[0]), "=r"((rr)[1]), "=r"((rr)[2]), "=r"((rr)[3]) : "r"(addr))

#define LDSM_X4_T(rr, addr) \
    asm volatile("ldmatrix.sync.aligned.m8n8.x4.trans.shared.b16 {%0,%1,%2,%3}, [%4];" \
        : "=r"((rr)[0]), "=r"((rr)[1]), "=r"((rr)[2]), "=r"((rr)[3]) : "r"(addr))

// f16 MMA, zero-init accumulator
#define MMA_F16(d, a, b0, b1) \
    asm volatile("mma.sync.aligned.m16n8k16.row.col.f32.f16.f16.f32 " \
        "{%0,%1,%2,%3}, {%4,%5,%6,%7}, {%8,%9}, {%10,%11,%12,%13};" \
        : "=f"((d)[0]), "=f"((d)[1]), "=f"((d)[2]), "=f"((d)[3]) \
        : "r"((a)[0]), "r"((a)[1]), "r"((a)[2]), "r"((a)[3]), "r"(b0), "r"(b1), \
          "f"(0.0f), "f"(0.0f), "f"(0.0f), "f"(0.0f))

// f16 MMA, accumulate
#define MMA_F16_ACC(d, a, b0, b1) \
    asm volatile("mma.sync.aligned.m16n8k16.row.col.f32.f16.f16.f32 " \
        "{%0,%1,%2,%3}, {%4,%5,%6,%7}, {%8,%9}, {%0,%1,%2,%3};" \
        : "+f"((d)[0]), "+f"((d)[1]), "+f"((d)[2]), "+f"((d)[3]) \
        : "r"((a)[0]), "r"((a)[1]), "r"((a)[2]), "r"((a)[3]), "r"(b0), "r"(b1))

// bf16 MMA, accumulate (attention O += P @ V)
#define MMA_BF16_ACC(d, a, b0, b1) \
    asm volatile("mma.sync.aligned.m16n8k16.row.col.f32.bf16.bf16.f32 " \
        "{%0,%1,%2,%3}, {%4,%5,%6,%7}, {%8,%9}, {%0,%1,%2,%3};" \
        : "+f"((d)[0]), "+f"((d)[1]), "+f"((d)[2]), "+f"((d)[3]) \
        : "r"((a)[0]), "r"((a)[1]), "r"((a)[2]), "r"((a)[3]), "r"(b0), "r"(b1))

__device__ __forceinline__ uint32_t cvt_bf16x2(float hi, float lo) {
    uint32_t r;
    asm("cvt.rn.bf16x2.f32 %0, %1, %2;" : "=r"(r) : "f"(hi), "f"(lo));
    return r;
}
__device__ __forceinline__ uint32_t cvt_f16x2(float hi, float lo) {
    uint32_t r;
    asm("cvt.rn.f16x2.f32 %0, %1, %2;" : "=r"(r) : "f"(hi), "f"(lo));
    return r;
}
__device__ __forceinline__ float ex2f(float x) {
    float r;
    asm("ex2.approx.ftz.f32 %0, %1;" : "=f"(r) : "f"(x));
    return r;
}

// ---------------------------------------------------------------------------
// Kernel A: fused 1x1 convs + 2x2 maxpool, f16 HMMA, single wave.
// grid 128 = (ph2 16, b 8), 512 threads; each CTA: 4 image rows (256 pos).
// x staged fp32 via cp.async (128KB), converted to f16 swizzled (64KB).
// ---------------------------------------------------------------------------
#define CV_WOFF  0u          // [h:2][oc:96][128B] f16          = 24576
#define CV_XS    24576u      // fp32 staging [c:128][1024B]     = 131072 (accbuf overlays)
#define CV_XB    155648u     // f16 x [q:4][c:128][128B]        = 65536
#define CV_SMEM  221184
#define AB_STRIDE 1040       // accbuf f32 row stride (bytes)

__global__ __launch_bounds__(512) void convpool_kernel(
    const float* __restrict__ x,
    const float* __restrict__ wth,
    const float* __restrict__ wph,
    const float* __restrict__ wg)
{
    extern __shared__ char smc[];
    const uint32_t sb = smem_u32(smc);
    const int ph2 = blockIdx.x, b = blockIdx.y;
    const int tid = threadIdx.x, wid = tid >> 5, lid = tid & 31;

    // ---- cp.async x fp32: rows c, 256 pos (1KB) each ----
    const char* xsrc = (const char*)(x + (size_t)b * (CC * HWV) + ph2 * 256);
    #pragma unroll
    for (int idx = tid; idx < 8192; idx += 512) {
        int c = idx >> 6, ch = idx & 63;
        cp_async16(sb + CV_XS + (uint32_t)(c * 1024 + ch * 16),
                   xsrc + (size_t)c * (HWV * 4) + ch * 16);
    }
    // ---- stage W (96x128 fp32 -> f16, swizzled c-halves), overlaps cp ----
    for (int idx = tid; idx < 96 * 32; idx += 512) {
        int oc = idx >> 5, c4 = idx & 31;
        const float4* wsrc;
        if (oc < 16)      wsrc = (const float4*)(wth + oc * 128) + c4;
        else if (oc < 32) wsrc = (const float4*)(wph + (oc - 16) * 128) + c4;
        else              wsrc = (const float4*)(wg  + (oc - 32) * 128) + c4;
        float4 v = *wsrc;
        uint2 pk;
        pk.x = cvt_f16x2(v.y, v.x);
        pk.y = cvt_f16x2(v.w, v.z);
        int c = c4 * 4, h = c >> 6, cin = c & 63;
        *(uint2*)(smc + CV_WOFF + h * 12288 + SWZ((uint32_t)(oc * 128 + cin * 2))) = pk;
    }
    CP_WAIT_ALL();
    __syncthreads();

    // ---- convert x fp32 -> f16 swizzled pos-quarters ----
    #pragma unroll
    for (int idx = tid; idx < 8192; idx += 512) {
        int c = idx >> 6, p4 = idx & 63;
        float4 v = *(const float4*)(smc + CV_XS + c * 1024 + p4 * 16);
        uint2 pk;
        pk.x = cvt_f16x2(v.y, v.x);
        pk.y = cvt_f16x2(v.w, v.z);
        int p = p4 * 4, q = p >> 6, pin = p & 63;
        *(uint2*)(smc + CV_XB + q * 16384 + SWZ((uint32_t)(c * 128 + pin * 2))) = pk;
    }
    __syncthreads();

    // ---- MMA: warp w -> pos group w*16 ----
    const int t = lid >> 3, r = lid & 7;
    const int rowsel = (t & 1) * 8 + r;
    const int khalf16 = (t >> 1) * 16;
    const int pg = wid * 16;
    const int xq = pg >> 6;
    const int pin = pg & 63;

    float acc[6][2][4];
    #pragma unroll
    for (int mt = 0; mt < 6; mt++)
        #pragma unroll
        for (int nt = 0; nt < 2; nt++)
            #pragma unroll
            for (int e = 0; e < 4; e++) acc[mt][nt][e] = 0.0f;

    #pragma unroll 2
    for (int ks = 0; ks < 8; ks++) {
        const int hk = ks >> 2, cq = ks & 3;
        uint32_t bfr[4];
        LDSM_X4_T(bfr, sb + CV_XB + xq * 16384 +
                  SWZ((uint32_t)((ks * 16 + (t & 1) * 8 + r) * 128 + pin * 2 + (t >> 1) * 16)));
        #pragma unroll
        for (int mt = 0; mt < 6; mt++) {
            uint32_t a[4];
            LDSM_X4(a, sb + CV_WOFF + hk * 12288 +
                    SWZ((uint32_t)((mt * 16 + rowsel) * 128 + cq * 32 + khalf16)));
            MMA_F16_ACC(acc[mt][0], a, bfr[0], bfr[1]);
            MMA_F16_ACC(acc[mt][1], a, bfr[2], bfr[3]);
        }
    }
    __syncthreads();   // staging region dead -> accbuf overlay

    // ---- accum -> smem fp32 accbuf [96 oc][256 pos] ----
    const int g = lid >> 2, tc = lid & 3;
    #pragma unroll
    for (int mt = 0; mt < 6; mt++)
        #pragma unroll
        for (int nt = 0; nt < 2; nt++) {
            int colb = (pg + nt * 8 + tc * 2) * 4;
            float2 lo = make_float2(acc[mt][nt][0], acc[mt][nt][1]);
            float2 hi = make_float2(acc[mt][nt][2], acc[mt][nt][3]);
            *(float2*)(smc + CV_XS + (mt * 16 + g)     * AB_STRIDE + colb) = lo;
            *(float2*)(smc + CV_XS + (mt * 16 + 8 + g) * AB_STRIDE + colb) = hi;
        }
    __syncthreads();

    // ---- theta (oc 0..15) -> Qf, pre-scaled by log2e ----
    for (int idx = tid; idx < 4096; idx += 512) {
        int p = idx >> 4, oc = idx & 15;
        float v = *(const float*)(smc + CV_XS + oc * AB_STRIDE + p * 4) * LG2E;
        Qf[((size_t)(b * HWV) + ph2 * 256 + p) * C8 + oc] = __float2half(v);
    }
    // ---- pool phi/g (oc 16..95): 2 pooled rows x 32 cols ----
    for (int idx = tid; idx < 80 * 64; idx += 512) {
        int cc = idx >> 6, rem = idx & 63;
        int pr = rem >> 5, pw = rem & 31;
        const char* rowp = smc + CV_XS + (16 + cc) * AB_STRIDE;
        int p0 = (pr * 128 + 2 * pw) * 4;
        float v0 = *(const float*)(rowp + p0);
        float v1 = *(const float*)(rowp + p0 + 4);
        float v2 = *(const float*)(rowp + p0 + 256);
        float v3 = *(const float*)(rowp + p0 + 260);
        float m = fmaxf(fmaxf(v0, v1), fmaxf(v2, v3));
        int pj = (2 * ph2 + pr) * 32 + pw;
        if (cc < 16)
            Kf[((size_t)(b * PJV) + pj) * C8 + cc] = __float2half(m);
        else
            Vg[((size_t)(b * PJV) + pj) * C2 + (cc - 16)] = __float2bfloat16(m);
    }
}

// ---------------------------------------------------------------------------
// Kernel B: HMMA flash attention. 1 CTA per (b, 256-query tile), 256 threads.
// Single wave (128 CTAs). Q(8KB)+K(32KB)+V(128KB) smem. Max-free softmax,
// exp via ex2 (Q pre-scaled by log2e). f16 S-MMA, bf16 O-MMA.
// ---------------------------------------------------------------------------
#define QOFF  0u
#define KOFF  8192u
#define VOFF  40960u

__global__ __launch_bounds__(256, 1) void attn_kernel()
{
    extern __shared__ char smc[];
    const uint32_t sb = smem_u32(smc);
    const int tid = threadIdx.x, wid = tid >> 5, lid = tid & 31;
    const int b = blockIdx.y, m0 = blockIdx.x * 256;

    // ---- async loads of Q/K/V into smem ----
    {
        const char* qsrc = (const char*)(Qf + ((size_t)(b * HWV) + m0) * C8);
        int m = tid;  // 0..255
        cp_async16(sb + QOFF + SWZ(m * 32),      qsrc + m * 32);
        cp_async16(sb + QOFF + SWZ(m * 32 + 16), qsrc + m * 32 + 16);

        const char* ksrc = (const char*)(Kf + (size_t)b * PJV * C8);
        #pragma unroll
        for (int j = tid; j < PJV; j += 256) {
            cp_async16(sb + KOFF + SWZ(j * 32),      ksrc + j * 32);
            cp_async16(sb + KOFF + SWZ(j * 32 + 16), ksrc + j * 32 + 16);
        }
        const char* vsrc = (const char*)(Vg + (size_t)b * PJV * C2);
        #pragma unroll
        for (int idx = tid; idx < PJV * 8; idx += 256)
            cp_async16(sb + VOFF + SWZ(idx * 16), vsrc + idx * 16);
        CP_WAIT_ALL();
    }
    __syncthreads();

    const int t  = lid >> 3, r = lid & 7;
    const int rowsel = (t & 1) * 8 + r;
    const int khalf  = (t >> 1) * 16;

    uint32_t qa[4], qb[4];
    LDSM_X4(qa, sb + QOFF + SWZ((uint32_t)((wid * 32 + rowsel) * 32 + khalf)));
    LDSM_X4(qb, sb + QOFF + SWZ((uint32_t)((wid * 32 + 16 + rowsel) * 32 + khalf)));

    float oacc[2][8][4];
    #pragma unroll
    for (int mt = 0; mt < 2; mt++)
        #pragma unroll
        for (int nt = 0; nt < 8; nt++)
            #pragma unroll
            for (int e = 0; e < 4; e++) oacc[mt][nt][e] = 0.0f;
    float lsum[2][2] = {{0.0f, 0.0f}, {0.0f, 0.0f}};

    const uint32_t kladdr_base = (uint32_t)(rowsel * 32 + khalf);
    const uint32_t vladdr_row  = (uint32_t)((t & 1) * 8 + r) * 128 + (uint32_t)((t >> 1) * 8) * 2;

    #pragma unroll 1
    for (int jt = 0; jt < 64; jt++) {
        const uint32_t j0 = (uint32_t)jt * 16;
        uint32_t kb[4];
        LDSM_X4(kb, sb + KOFF + SWZ(kladdr_base + j0 * 32));

        float sA0[4], sA1[4], sB0[4], sB1[4];
        MMA_F16(sA0, qa, kb[0], kb[2]);
        MMA_F16(sA1, qa, kb[1], kb[3]);
        MMA_F16(sB0, qb, kb[0], kb[2]);
        MMA_F16(sB1, qb, kb[1], kb[3]);

        uint32_t pA[4], pB[4];
        {
            float e0 = ex2f(sA0[0]), e1 = ex2f(sA0[1]), e2 = ex2f(sA0[2]), e3 = ex2f(sA0[3]);
            float f0 = ex2f(sA1[0]), f1 = ex2f(sA1[1]), f2 = ex2f(sA1[2]), f3 = ex2f(sA1[3]);
            lsum[0][0] += e0 + e1 + f0 + f1;
            lsum[0][1] += e2 + e3 + f2 + f3;
            pA[0] = cvt_bf16x2(e1, e0); pA[1] = cvt_bf16x2(e3, e2);
            pA[2] = cvt_bf16x2(f1, f0); pA[3] = cvt_bf16x2(f3, f2);
        }
        {
            float e0 = ex2f(sB0[0]), e1 = ex2f(sB0[1]), e2 = ex2f(sB0[2]), e3 = ex2f(sB0[3]);
            float f0 = ex2f(sB1[0]), f1 = ex2f(sB1[1]), f2 = ex2f(sB1[2]), f3 = ex2f(sB1[3]);
            lsum[1][0] += e0 + e1 + f0 + f1;
            lsum[1][1] += e2 + e3 + f2 + f3;
            pB[0] = cvt_bf16x2(e1, e0); pB[1] = cvt_bf16x2(e3, e2);
            pB[2] = cvt_bf16x2(f1, f0); pB[3] = cvt_bf16x2(f3, f2);
        }

        #pragma unroll
        for (int cq = 0; cq < 4; cq++) {
            uint32_t vb[4];
            LDSM_X4_T(vb, sb + VOFF + SWZ(vladdr_row + j0 * 128 + (uint32_t)cq * 32));
            MMA_BF16_ACC(oacc[0][2 * cq],     pA, vb[0], vb[1]);
            MMA_BF16_ACC(oacc[0][2 * cq + 1], pA, vb[2], vb[3]);
            MMA_BF16_ACC(oacc[1][2 * cq],     pB, vb[0], vb[1]);
            MMA_BF16_ACC(oacc[1][2 * cq + 1], pB, vb[2], vb[3]);
        }
    }

    #pragma unroll
    for (int mt = 0; mt < 2; mt++)
        #pragma unroll
        for (int hh = 0; hh < 2; hh++) {
            float l = lsum[mt][hh];
            l += __shfl_xor_sync(0xffffffffu, l, 1);
            l += __shfl_xor_sync(0xffffffffu, l, 2);
            lsum[mt][hh] = 1.0f / l;
        }

    const int g = lid >> 2, tc = lid & 3;
    #pragma unroll
    for (int mt = 0; mt < 2; mt++) {
        int mrow = m0 + wid * 32 + mt * 16 + g;
        __half* o0 = Og + ((size_t)(b * HWV) + mrow) * C2;
        __half* o1 = o0 + 8 * C2;
        #pragma unroll
        for (int nt = 0; nt < 8; nt++) {
            uint32_t w0 = cvt_f16x2(oacc[mt][nt][1] * lsum[mt][0],
                                    oacc[mt][nt][0] * lsum[mt][0]);
            uint32_t w1 = cvt_f16x2(oacc[mt][nt][3] * lsum[mt][1],
                                    oacc[mt][nt][2] * lsum[mt][1]);
            *(uint32_t*)(o0 + nt * 8 + tc * 2) = w0;
            *(uint32_t*)(o1 + nt * 8 + tc * 2) = w1;
        }
    }
}

// ---------------------------------------------------------------------------
// Kernel C: out = x + gamma * (w_o @ o), f16 HMMA, single wave.
// grid (16 itiles, 8 b) = 128 CTAs, 512 threads. Per CTA: 256 pos x 128 oc.
// Warp (posg = wid>>2 -> 64 pos, ocg = wid&3 -> 32 oc).
// ---------------------------------------------------------------------------
#define EP_WOFF 0u           // wo f16 [128 oc][128B]  = 16384
#define EP_OOFF 16384u       // o  f16 [256 pos][128B] = 32768
#define EP_SMEM 49152

__global__ __launch_bounds__(512) void epilogue_kernel(
    const float* __restrict__ x,
    const float* __restrict__ wo,
    const float* __restrict__ gptr,
    float* __restrict__ out)
{
    extern __shared__ char smc[];
    const uint32_t sb = smem_u32(smc);
    const int it = blockIdx.x, b = blockIdx.y;
    const int i0 = it * 256;
    const int tid = threadIdx.x, wid = tid >> 5, lid = tid & 31;

    // ---- cp.async o tile (256 pos x 64 c f16 = 32KB) ----
    const char* osrc = (const char*)(Og + ((size_t)(b * HWV) + i0) * C2);
    #pragma unroll
    for (int idx = tid; idx < 2048; idx += 512) {
        int p = idx >> 3, ch = idx & 7;
        cp_async16(sb + EP_OOFF + SWZ((uint32_t)(p * 128 + ch * 16)), osrc + idx * 16);
    }
    // ---- stage wo fp32 -> f16 (128 oc x 64 c) ----
    for (int idx = tid; idx < 2048; idx += 512) {
        int oc = idx >> 4, c4 = idx & 15;
        float4 v = *((const float4*)(wo + oc * 64) + c4);
        uint2 pk;
        pk.x = cvt_f16x2(v.y, v.x);
        pk.y = cvt_f16x2(v.w, v.z);
        *(uint2*)(smc + EP_WOFF + SWZ((uint32_t)(oc * 128 + c4 * 8))) = pk;
    }
    CP_WAIT_ALL();
    __syncthreads();

    const int t = lid >> 3, r = lid & 7;
    const int rowsel = (t & 1) * 8 + r;
    const int khalf16 = (t >> 1) * 16;
    const int posg = wid >> 2, ocg = wid & 3;
    const int pos0 = posg * 64, oc0 = ocg * 32;

    float acc[2][8][4];
    #pragma unroll
    for (int mt = 0; mt < 2; mt++)
        #pragma unroll
        for (int nt = 0; nt < 8; nt++)
            #pragma unroll
            for (int e = 0; e < 4; e++) acc[mt][nt][e] = 0.0f;

    #pragma unroll
    for (int ks = 0; ks < 4; ks++) {
        uint32_t a0[4], a1[4];
        LDSM_X4(a0, sb + EP_WOFF + SWZ((uint32_t)((oc0 + rowsel) * 128 + ks * 32 + khalf16)));
        LDSM_X4(a1, sb + EP_WOFF + SWZ((uint32_t)((oc0 + 16 + rowsel) * 128 + ks * 32 + khalf16)));
        #pragma unroll
        for (int nt4 = 0; nt4 < 4; nt4++) {
            uint32_t bfr[4];
            LDSM_X4(bfr, sb + EP_OOFF +
                    SWZ((uint32_t)((pos0 + nt4 * 16 + rowsel) * 128 + ks * 32 + khalf16)));
            MMA_F16_ACC(acc[0][2 * nt4],     a0, bfr[0], bfr[2]);
            MMA_F16_ACC(acc[0][2 * nt4 + 1], a0, bfr[1], bfr[3]);
            MMA_F16_ACC(acc[1][2 * nt4],     a1, bfr[0], bfr[2]);
            MMA_F16_ACC(acc[1][2 * nt4 + 1], a1, bfr[1], bfr[3]);
        }
    }

    // ---- out = x + gamma*acc ----
    const float gamma = __ldg(gptr);
    const int g = lid >> 2, tc = lid & 3;
    #pragma unroll
    for (int mt = 0; mt < 2; mt++) {
        int ocb = oc0 + mt * 16;
        #pragma unroll
        for (int nt = 0; nt < 8; nt++) {
            int pos = i0 + pos0 + nt * 8 + tc * 2;
            size_t off0 = ((size_t)(b * CC) + ocb + g) * HWV + pos;
            size_t off1 = ((size_t)(b * CC) + ocb + 8 + g) * HWV + pos;
            float2 xv0 = *(const float2*)(x + off0);
            float2 xv1 = *(const float2*)(x + off1);
            float2 w0, w1;
            w0.x = fmaf(gamma, acc[mt][nt][0], xv0.x);
            w0.y = fmaf(gamma, acc[mt][nt][1], xv0.y);
            w1.x = fmaf(gamma, acc[mt][nt][2], xv1.x);
            w1.y = fmaf(gamma, acc[mt][nt][3], xv1.y);
            *(float2*)(out + off0) = w0;
            *(float2*)(out + off1) = w1;
        }
    }
}

// ---------------------------------------------------------------------------
extern "C" void kernel_launch(void* const* d_in, const int* in_sizes, int n_in,
                              void* d_out, int out_size)
{
    const float* x   = (const float*)d_in[0];
    const float* wth = (const float*)d_in[1];
    const float* wph = (const float*)d_in[2];
    const float* wg  = (const float*)d_in[3];
    const float* wo  = (const float*)d_in[4];
    const float* gmm = (const float*)d_in[5];
    float* out = (float*)d_out;

    const int SMEM_A = CV_SMEM;                    // 221184
    const int SMEM_B = 8192 + 32768 + 131072;      // 172032
    const int SMEM_C = EP_SMEM;                    // 49152

    cudaFuncSetAttribute(convpool_kernel, cudaFuncAttributeMaxDynamicSharedMemorySize, SMEM_A);
    cudaFuncSetAttribute(attn_kernel,     cudaFuncAttributeMaxDynamicSharedMemorySize, SMEM_B);
    cudaFuncSetAttribute(epilogue_kernel, cudaFuncAttributeMaxDynamicSharedMemorySize, SMEM_C);

    convpool_kernel<<<dim3(16, 8), 512, SMEM_A>>>(x, wth, wph, wg);
    attn_kernel<<<dim3(16, 8), 256, SMEM_B>>>();
    epilogue_kernel<<<dim3(16, 8), 512, SMEM_C>>>(x, wo, gmm, out);
}